// round 9
// baseline (speedup 1.0000x reference)
#include <cuda_runtime.h>
#include <cuda_bf16.h>

#define B_TOT 4096
#define N_IN  512
#define N_TOT 2048
#define N_EV  1536
#define N_OUT 256

#define KB    128          // eval nodes per block (GEMM M)
#define NBLK  (N_EV / KB)  // 12
#define SUB   16           // triangle sub-block
#define BT    64           // batch columns per CTA (GEMM N)
#define NCTA  (B_TOT / BT) // 64
#define NTHR  256          // 8 warps
#define CH    64           // K-chunk

#define OS_PAD   68        // zsm/osm_blk row stride (floats)
#define WSEQ_PAD 129
#define WT_STRIDE 144      // bytes per bf16 tile row (9 x 16B -> ldsm conflict-free)

// tile-buffer internal offsets (relative to buffer base)
#define W_HI  0                       // 128 x 144 = 18432
#define W_LO  18432
#define O_HI  36864                   // 64 x 144 = 9216
#define O_LO  46080
#define TILE_BYTES 55296
// double-buffered tiles + solve arrays
#define ZSM_OFF (2 * TILE_BYTES)              // float [128][68] = 34816
#define OSB_OFF (ZSM_OFF + 34816)
#define BSM_OFF (OSB_OFF + 34816)
#define SMEM_BYTES (BSM_OFF + 512)            // 180736

// global bf16 hi/lo tensors (pre-pass W; running outputs in [batch][node])
__device__ __nv_bfloat16 g_Whi[(size_t)N_EV * N_TOT];
__device__ __nv_bfloat16 g_Wlo[(size_t)N_EV * N_TOT];
__device__ __nv_bfloat16 g_ohi[(size_t)B_TOT * N_TOT];
__device__ __nv_bfloat16 g_olo[(size_t)B_TOT * N_TOT];

typedef unsigned long long ull;
typedef unsigned int uint;
typedef unsigned short ushort;

__device__ __forceinline__ uint smem_u32_of(const void* p) {
    uint a; asm("{ .reg .u64 t; cvta.to.shared.u64 t, %1; cvt.u32.u64 %0, t; }"
                : "=r"(a) : "l"(p)); return a;
}
__device__ __forceinline__ void ldsm_x4(uint* r, uint a) {
    asm volatile("ldmatrix.sync.aligned.m8n8.x4.shared.b16 {%0,%1,%2,%3}, [%4];"
                 : "=r"(r[0]), "=r"(r[1]), "=r"(r[2]), "=r"(r[3]) : "r"(a));
}
__device__ __forceinline__ void mma16816(float* d, const uint* a, const uint* b) {
    asm volatile("mma.sync.aligned.m16n8k16.row.col.f32.bf16.bf16.f32 "
                 "{%0,%1,%2,%3}, {%4,%5,%6,%7}, {%8,%9}, {%0,%1,%2,%3};"
                 : "+f"(d[0]), "+f"(d[1]), "+f"(d[2]), "+f"(d[3])
                 : "r"(a[0]), "r"(a[1]), "r"(a[2]), "r"(a[3]),
                   "r"(b[0]), "r"(b[1]));
}

// ---- cp.async (sm_80+ baseline) ----
__device__ __forceinline__ void cp_async16(uint dst, const void* src) {
    asm volatile("cp.async.cg.shared.global [%0], [%1], 16;"
                 :: "r"(dst), "l"(__cvta_generic_to_global(src)) : "memory");
}
#define CP_COMMIT() asm volatile("cp.async.commit_group;" ::: "memory")
#define CP_WAIT0()  asm volatile("cp.async.wait_group 0;" ::: "memory")

// packed fp32x2 (solve phase)
__device__ __forceinline__ ull pack2(float lo, float hi) {
    ull r; asm("mov.b64 %0, {%1, %2};" : "=l"(r) : "f"(lo), "f"(hi)); return r;
}
__device__ __forceinline__ float2 unpack2(ull v) {
    float2 r; asm("mov.b64 {%0, %1}, %2;" : "=f"(r.x), "=f"(r.y) : "l"(v)); return r;
}
__device__ __forceinline__ void ffma2(ull& d, ull a, ull b) {
    asm("fma.rn.f32x2 %0, %1, %2, %0;" : "+l"(d) : "l"(a), "l"(b));
}
__device__ __forceinline__ float fast_sigmoid5(float z) {
    float t = fminf(fmaxf(5.0f * z, -60.0f), 60.0f);
    float e; asm("ex2.approx.f32 %0, %1;" : "=f"(e) : "f"(-t * 1.4426950408889634f));
    float d = 1.0f + e;
    float o; asm("rcp.approx.f32 %0, %1;" : "=f"(o) : "f"(d));
    return o;
}
__device__ __forceinline__ void split_bf16(float v, ushort& h, ushort& l) {
    __nv_bfloat16 hb = __float2bfloat16_rn(v);
    __nv_bfloat16 lb = __float2bfloat16_rn(v - __bfloat162float(hb));
    h = __bfloat16_as_ushort(hb);
    l = __bfloat16_as_ushort(lb);
}

// ---------------- pre-pass: W fp32 -> bf16 hi/lo ----------------
__global__ void convW_kernel(const float* __restrict__ W) {
    int i = blockIdx.x * 256 + threadIdx.x;        // float4 index
    float4 v = ((const float4*)W)[i];
    ushort h0, h1, h2, h3, l0, l1, l2, l3;
    split_bf16(v.x, h0, l0); split_bf16(v.y, h1, l1);
    split_bf16(v.z, h2, l2); split_bf16(v.w, h3, l3);
    ((uint2*)g_Whi)[i] = make_uint2(((uint)h1 << 16) | h0, ((uint)h3 << 16) | h2);
    ((uint2*)g_Wlo)[i] = make_uint2(((uint)l1 << 16) | l0, ((uint)l3 << 16) | l2);
}

extern __shared__ char smemc[];

// stage one 64-K chunk (async): W hi/lo [128][64] + o hi/lo [64][64]
#define STAGE_CHUNK(P0, BUFOFF) do {                                          \
    for (int idx = tid; idx < KB * 8; idx += NTHR) {                          \
        int n = idx >> 3, j8 = idx & 7;                                       \
        size_t g = (size_t)(erow0 + n) * N_TOT + (P0) + j8 * 8;               \
        uint d0 = smem_base + (BUFOFF) + W_HI + n * WT_STRIDE + j8 * 16;      \
        cp_async16(d0, g_Whi + g);                                            \
        cp_async16(d0 + (W_LO - W_HI), g_Wlo + g);                            \
    }                                                                         \
    for (int idx = tid; idx < BT * 8; idx += NTHR) {                          \
        int n = idx >> 3, j8 = idx & 7;                                       \
        size_t g = (size_t)(c0 + n) * N_TOT + (P0) + j8 * 8;                  \
        uint d0 = smem_base + (BUFOFF) + O_HI + n * WT_STRIDE + j8 * 16;      \
        cp_async16(d0, g_ohi + g);                                            \
        cp_async16(d0 + (O_LO - O_HI), g_olo + g);                            \
    }                                                                         \
} while (0)

__global__ __launch_bounds__(NTHR, 1)
void neat_ff_kernel(const float* __restrict__ x,
                    const float* __restrict__ W,
                    const float* __restrict__ bias,
                    float* __restrict__ out)
{
    float* zsm     = (float*)(smemc + ZSM_OFF);
    float* osm_blk = (float*)(smemc + OSB_OFF);
    float* bsm     = (float*)(smemc + BSM_OFF);

    const int  tid = threadIdx.x;
    const int  wid = tid >> 5;
    const int  lid = tid & 31;
    const int  c0  = blockIdx.x * BT;
    const uint smem_base = smem_u32_of(smemc);

    // ---- init: x rows -> g_ohi/g_olo (contiguous) ----
    for (int idx = tid; idx < BT * (N_IN / 4); idx += NTHR) {
        int c = idx >> 7, j4 = idx & 127;
        float4 v = *(const float4*)(x + (size_t)(c0 + c) * N_IN + j4 * 4);
        ushort h0, h1, h2, h3, l0, l1, l2, l3;
        split_bf16(v.x, h0, l0); split_bf16(v.y, h1, l1);
        split_bf16(v.z, h2, l2); split_bf16(v.w, h3, l3);
        size_t g = (size_t)(c0 + c) * N_TOT + j4 * 4;
        *(uint2*)(g_ohi + g) = make_uint2(((uint)h1 << 16) | h0, ((uint)h3 << 16) | h2);
        *(uint2*)(g_olo + g) = make_uint2(((uint)l1 << 16) | l0, ((uint)l3 << 16) | l2);
    }
    __syncthreads();

    // per-thread fragment offsets (relative to buffer base)
    const int r0 = wid * 16;                                  // warp's 16 M-rows
    const uint oA = (uint)(r0 + (lid & 15)) * WT_STRIDE + (uint)(lid >> 4) * 16;
    const int  bg = lid >> 3;                                 // 0..3
    const uint oB = (uint)(((bg >> 1) * 8) + (lid & 7)) * WT_STRIDE + (uint)(bg & 1) * 16;

    const int ng  = tid >> 3;   // 0..31 node groups of 4 (solve phase)
    const int cg  = tid & 7;    // 0..7  col groups of 8
    const int ng4 = ng * 4;

    for (int t = 0; t < NBLK; ++t) {
        const int start = N_IN + t * KB;
        const int erow0 = t * KB;

        if (tid < KB) bsm[tid] = bias[erow0 + tid];

        // ================= pipelined HMMA GEMM (M=128, N=64) =================
        float d[8][4];
        #pragma unroll
        for (int nt = 0; nt < 8; ++nt)
            #pragma unroll
            for (int k = 0; k < 4; ++k) d[nt][k] = 0.0f;

        const int nchunk = start / CH;

        STAGE_CHUNK(0, 0u);            // prologue: chunk 0 -> buf0
        CP_COMMIT();

        for (int ci = 0; ci < nchunk; ++ci) {
            const uint bufoff = (uint)(ci & 1) * TILE_BYTES;
            CP_WAIT0();                // chunk ci landed (own group)
            __syncthreads();           // all threads waited; prev compute done
            if (ci + 1 < nchunk) {     // prefetch next into other buffer
                STAGE_CHUNK((ci + 1) * CH, (uint)((ci + 1) & 1) * TILE_BYTES);
                CP_COMMIT();
            }

            const uint aA = smem_base + bufoff + oA;
            const uint aB = smem_base + bufoff + oB;
            #pragma unroll
            for (int kk = 0; kk < 4; ++kk) {
                const uint ko = (uint)kk * 32;
                uint Ah[4], Al[4], Bh[16], Bl[16];
                ldsm_x4(Ah, aA + W_HI + ko);
                ldsm_x4(Al, aA + W_LO + ko);
                #pragma unroll
                for (int gq = 0; gq < 4; ++gq) {
                    ldsm_x4(Bh + gq * 4, aB + O_HI + gq * 16 * WT_STRIDE + ko);
                    ldsm_x4(Bl + gq * 4, aB + O_LO + gq * 16 * WT_STRIDE + ko);
                }
                #pragma unroll
                for (int nt = 0; nt < 8; ++nt) {
                    const uint* bh = Bh + (nt >> 1) * 4 + (nt & 1) * 2;
                    const uint* bl = Bl + (nt >> 1) * 4 + (nt & 1) * 2;
                    mma16816(d[nt], Ah, bh);   // Wh*oh
                    mma16816(d[nt], Al, bh);   // Wl*oh
                    mma16816(d[nt], Ah, bl);   // Wh*ol
                }
            }
        }

        // ---- write fragments (z pre-bias) into zsm ----
        {
            int rl = r0 + (lid >> 2), cb = (lid & 3) * 2;
            #pragma unroll
            for (int nt = 0; nt < 8; ++nt) {
                *(float2*)&zsm[rl * OS_PAD + nt * 8 + cb]       = make_float2(d[nt][0], d[nt][1]);
                *(float2*)&zsm[(rl + 8) * OS_PAD + nt * 8 + cb] = make_float2(d[nt][2], d[nt][3]);
            }
        }
        __syncthreads();

        // ---- stage in-block fp32 W tile (unions into dead tile buffers) ----
        float* wseq = (float*)smemc;
        for (int idx = tid; idx < KB * KB; idx += NTHR) {
            int n = idx / KB, j = idx % KB;
            wseq[n * WSEQ_PAD + j] = W[(size_t)(erow0 + n) * N_TOT + start + j];
        }
        __syncthreads();

        // ---- load this thread's z tile into packed registers (4 nodes x 8 cols)
        ull acc2[4][4];
        #pragma unroll
        for (int k = 0; k < 4; ++k) {
            const float* zr = zsm + (ng4 + k) * OS_PAD + cg * 8;
            #pragma unroll
            for (int h = 0; h < 4; ++h)
                acc2[k][h] = pack2(zr[2 * h], zr[2 * h + 1]);
        }

        // ---- hierarchical sequential solve: 8 x (16-triangle + rank-16) ----
        for (int s = 0; s < 8; ++s) {
            if ((ng >> 2) == s) {
                #pragma unroll
                for (int k = 0; k < 4; ++k)
                    #pragma unroll
                    for (int h = 0; h < 4; ++h) {
                        float2 v = unpack2(acc2[k][h]);
                        zsm[(ng4 + k) * OS_PAD + cg * 8 + 2 * h]     = v.x;
                        zsm[(ng4 + k) * OS_PAD + cg * 8 + 2 * h + 1] = v.y;
                    }
            }
            __syncthreads();

            if (tid < BT) {
                const int col  = tid;
                const int base = s * SUB;
                float oreg[SUB];
                #pragma unroll
                for (int i = 0; i < SUB; ++i) {
                    float z = zsm[(base + i) * OS_PAD + col] + bsm[base + i];
                    #pragma unroll
                    for (int j = 0; j < i; ++j)
                        z += wseq[(base + i) * WSEQ_PAD + (base + j)] * oreg[j];
                    float o = fast_sigmoid5(z);
                    oreg[i] = o;
                    osm_blk[(base + i) * OS_PAD + col] = o;
                }
            }
            __syncthreads();

            if (ng >= 4 * (s + 1)) {
                #pragma unroll
                for (int j = 0; j < SUB; ++j) {
                    int jj = s * SUB + j;
                    const ull* o2 = (const ull*)&osm_blk[jj * OS_PAD + cg * 8];
                    ull ov[4] = {o2[0], o2[1], o2[2], o2[3]};
                    #pragma unroll
                    for (int k = 0; k < 4; ++k) {
                        float w = wseq[(ng4 + k) * WSEQ_PAD + jj];
                        ull wp = pack2(w, w);
                        #pragma unroll
                        for (int h = 0; h < 4; ++h)
                            ffma2(acc2[k][h], wp, ov[h]);
                    }
                }
            }
        }
        __syncthreads();

        // ---- commit block outputs as bf16 hi/lo ([batch][node] layout) ----
        for (int idx = tid; idx < BT * (KB / 2); idx += NTHR) {
            int c = idx >> 6, j2 = idx & 63;
            float o0 = osm_blk[(2 * j2) * OS_PAD + c];
            float o1 = osm_blk[(2 * j2 + 1) * OS_PAD + c];
            ushort h0, h1, l0, l1;
            split_bf16(o0, h0, l0);
            split_bf16(o1, h1, l1);
            size_t g = (size_t)(c0 + c) * N_TOT + start + 2 * j2;
            *(uint*)(g_ohi + g) = ((uint)h1 << 16) | h0;
            *(uint*)(g_olo + g) = ((uint)l1 << 16) | l0;
        }
        if (start >= N_TOT - N_OUT) {
            const int off = start - (N_TOT - N_OUT);
            for (int idx = tid; idx < KB * BT; idx += NTHR) {
                int j = idx % KB, c = idx / KB;
                out[(c0 + c) * N_OUT + off + j] = osm_blk[j * OS_PAD + c];
            }
        }
        __syncthreads();   // commit + wseq/buffer reads done before next block
    }
}

extern "C" void kernel_launch(void* const* d_in, const int* in_sizes, int n_in,
                              void* d_out, int out_size)
{
    const float* x    = (const float*)d_in[0];
    const float* W    = (const float*)d_in[1];
    const float* bias = (const float*)d_in[2];
    float* out        = (float*)d_out;

    convW_kernel<<<(N_EV * N_TOT / 4) / 256, 256>>>(W);

    cudaFuncSetAttribute(neat_ff_kernel,
                         cudaFuncAttributeMaxDynamicSharedMemorySize, SMEM_BYTES);
    neat_ff_kernel<<<NCTA, NTHR, SMEM_BYTES>>>(x, W, bias, out);
}

// round 10
// speedup vs baseline: 1.4067x; 1.4067x over previous
#include <cuda_runtime.h>
#include <cuda_bf16.h>

#define B_TOT 4096
#define N_IN  512
#define N_TOT 2048
#define N_EV  1536
#define N_OUT 256

#define KB    128          // eval nodes per block (GEMM M)
#define NBLK  (N_EV / KB)  // 12
#define SUB   16           // triangle sub-block
#define BT    32           // batch columns per CTA (GEMM N)
#define NCTA  (B_TOT / BT) // 128
#define NTHR  512          // 16 warps = 4 per SMSP (K-split GEMM)
#define CH    128          // K-chunk

#define OS_PAD   36
#define WSEQ_PAD 129
#define WT_STRIDE 272      // bytes per bf16 tile row (17 x 16B -> conflict-free)

// tile-buffer internal offsets (relative to buffer base)
#define W_HI  0                       // 128 x 272 = 34816
#define W_LO  34816
#define O_HI  69632                   // 32 x 272 = 8704
#define O_LO  78336
#define TILE_BYTES 87040
// double-buffered tiles + solve arrays
#define ZSMA_OFF (2 * TILE_BYTES)             // float [128][36] = 18432 (K-half 0)
#define ZSMB_OFF (ZSMA_OFF + 18432)           // float [128][36]         (K-half 1)
#define OSB_OFF  (ZSMB_OFF + 18432)
#define BSM_OFF  (OSB_OFF + 18432)
#define SMEM_BYTES (BSM_OFF + 512)            // 229888 (< 232448 limit)

// global bf16 hi/lo tensors (pre-pass W; running outputs in [batch][node])
__device__ __nv_bfloat16 g_Whi[(size_t)N_EV * N_TOT];
__device__ __nv_bfloat16 g_Wlo[(size_t)N_EV * N_TOT];
__device__ __nv_bfloat16 g_ohi[(size_t)B_TOT * N_TOT];
__device__ __nv_bfloat16 g_olo[(size_t)B_TOT * N_TOT];

typedef unsigned long long ull;
typedef unsigned int uint;
typedef unsigned short ushort;

__device__ __forceinline__ uint smem_u32_of(const void* p) {
    uint a; asm("{ .reg .u64 t; cvta.to.shared.u64 t, %1; cvt.u32.u64 %0, t; }"
                : "=r"(a) : "l"(p)); return a;
}
__device__ __forceinline__ void ldsm_x4(uint* r, uint a) {
    asm volatile("ldmatrix.sync.aligned.m8n8.x4.shared.b16 {%0,%1,%2,%3}, [%4];"
                 : "=r"(r[0]), "=r"(r[1]), "=r"(r[2]), "=r"(r[3]) : "r"(a));
}
__device__ __forceinline__ void mma16816(float* d, const uint* a, const uint* b) {
    asm volatile("mma.sync.aligned.m16n8k16.row.col.f32.bf16.bf16.f32 "
                 "{%0,%1,%2,%3}, {%4,%5,%6,%7}, {%8,%9}, {%0,%1,%2,%3};"
                 : "+f"(d[0]), "+f"(d[1]), "+f"(d[2]), "+f"(d[3])
                 : "r"(a[0]), "r"(a[1]), "r"(a[2]), "r"(a[3]),
                   "r"(b[0]), "r"(b[1]));
}

// ---- cp.async (sm_80+ baseline) ----
__device__ __forceinline__ void cp_async16(uint dst, const void* src) {
    asm volatile("cp.async.cg.shared.global [%0], [%1], 16;"
                 :: "r"(dst), "l"(__cvta_generic_to_global(src)) : "memory");
}
#define CP_COMMIT() asm volatile("cp.async.commit_group;" ::: "memory")
#define CP_WAIT1()  asm volatile("cp.async.wait_group 1;" ::: "memory")
#define CP_WAIT0()  asm volatile("cp.async.wait_group 0;" ::: "memory")

// packed fp32x2 (solve phase)
__device__ __forceinline__ ull pack2(float lo, float hi) {
    ull r; asm("mov.b64 %0, {%1, %2};" : "=l"(r) : "f"(lo), "f"(hi)); return r;
}
__device__ __forceinline__ float2 unpack2(ull v) {
    float2 r; asm("mov.b64 {%0, %1}, %2;" : "=f"(r.x), "=f"(r.y) : "l"(v)); return r;
}
__device__ __forceinline__ void ffma2(ull& d, ull a, ull b) {
    asm("fma.rn.f32x2 %0, %1, %2, %0;" : "+l"(d) : "l"(a), "l"(b));
}
__device__ __forceinline__ float fast_sigmoid5(float z) {
    float t = fminf(fmaxf(5.0f * z, -60.0f), 60.0f);
    float e; asm("ex2.approx.f32 %0, %1;" : "=f"(e) : "f"(-t * 1.4426950408889634f));
    float d = 1.0f + e;
    float o; asm("rcp.approx.f32 %0, %1;" : "=f"(o) : "f"(d));
    return o;
}
__device__ __forceinline__ void split_bf16(float v, ushort& h, ushort& l) {
    __nv_bfloat16 hb = __float2bfloat16_rn(v);
    __nv_bfloat16 lb = __float2bfloat16_rn(v - __bfloat162float(hb));
    h = __bfloat16_as_ushort(hb);
    l = __bfloat16_as_ushort(lb);
}

// ---------------- pre-pass: W fp32 -> bf16 hi/lo ----------------
__global__ void convW_kernel(const float* __restrict__ W) {
    int i = blockIdx.x * 256 + threadIdx.x;        // float4 index
    float4 v = ((const float4*)W)[i];
    ushort h0, h1, h2, h3, l0, l1, l2, l3;
    split_bf16(v.x, h0, l0); split_bf16(v.y, h1, l1);
    split_bf16(v.z, h2, l2); split_bf16(v.w, h3, l3);
    ((uint2*)g_Whi)[i] = make_uint2(((uint)h1 << 16) | h0, ((uint)h3 << 16) | h2);
    ((uint2*)g_Wlo)[i] = make_uint2(((uint)l1 << 16) | l0, ((uint)l3 << 16) | l2);
}

extern __shared__ char smemc[];

// stage one 128-K chunk (async): W hi/lo [128][128] + o hi/lo [32][128]
#define STAGE_CHUNK(P0, BUFOFF) do {                                          \
    for (int idx = tid; idx < KB * 16; idx += NTHR) {                         \
        int n = idx >> 4, j8 = idx & 15;                                      \
        size_t g = (size_t)(erow0 + n) * N_TOT + (P0) + j8 * 8;               \
        uint d0 = smem_base + (BUFOFF) + W_HI + n * WT_STRIDE + j8 * 16;      \
        cp_async16(d0, g_Whi + g);                                            \
        cp_async16(d0 + (W_LO - W_HI), g_Wlo + g);                            \
    }                                                                         \
    for (int idx = tid; idx < BT * 16; idx += NTHR) {                         \
        int n = idx >> 4, j8 = idx & 15;                                      \
        size_t g = (size_t)(c0 + n) * N_TOT + (P0) + j8 * 8;                  \
        uint d0 = smem_base + (BUFOFF) + O_HI + n * WT_STRIDE + j8 * 16;      \
        cp_async16(d0, g_ohi + g);                                            \
        cp_async16(d0 + (O_LO - O_HI), g_olo + g);                            \
    }                                                                         \
} while (0)

__global__ __launch_bounds__(NTHR, 1)
void neat_ff_kernel(const float* __restrict__ x,
                    const float* __restrict__ W,
                    const float* __restrict__ bias,
                    float* __restrict__ out)
{
    float* zsma    = (float*)(smemc + ZSMA_OFF);
    float* zsmb    = (float*)(smemc + ZSMB_OFF);
    float* osm_blk = (float*)(smemc + OSB_OFF);
    float* bsm     = (float*)(smemc + BSM_OFF);

    const int  tid = threadIdx.x;
    const int  wid = tid >> 5;
    const int  lid = tid & 31;
    const int  c0  = blockIdx.x * BT;
    const uint smem_base = smem_u32_of(smemc);

    // ---- init: x rows -> g_ohi/g_olo (contiguous) ----
    for (int idx = tid; idx < BT * (N_IN / 4); idx += NTHR) {
        int c = idx >> 7, j4 = idx & 127;
        float4 v = *(const float4*)(x + (size_t)(c0 + c) * N_IN + j4 * 4);
        ushort h0, h1, h2, h3, l0, l1, l2, l3;
        split_bf16(v.x, h0, l0); split_bf16(v.y, h1, l1);
        split_bf16(v.z, h2, l2); split_bf16(v.w, h3, l3);
        size_t g = (size_t)(c0 + c) * N_TOT + j4 * 4;
        *(uint2*)(g_ohi + g) = make_uint2(((uint)h1 << 16) | h0, ((uint)h3 << 16) | h2);
        *(uint2*)(g_olo + g) = make_uint2(((uint)l1 << 16) | l0, ((uint)l3 << 16) | l2);
    }
    __syncthreads();

    // GEMM warp mapping: warp pairs share an M-slice, split K halves
    const int mwid = wid >> 1;        // 0..7: M-slice (16 rows)
    const int kh   = wid & 1;         // 0/1:  K half of each chunk
    const int r0   = mwid * 16;
    const uint oA = (uint)(r0 + (lid & 15)) * WT_STRIDE + (uint)(lid >> 4) * 16;
    const int  bg = lid >> 3;         // 0..3
    const uint oB = (uint)(((bg >> 1) * 8) + (lid & 7)) * WT_STRIDE + (uint)(bg & 1) * 16;

    const int ng  = tid >> 3;   // solve: node groups of 4 (threads < 256 only)
    const int cg  = tid & 7;    // solve: col groups of 4
    const int ng4 = ng * 4;

    for (int t = 0; t < NBLK; ++t) {
        const int start = N_IN + t * KB;
        const int erow0 = t * KB;

        if (tid < KB) bsm[tid] = bias[erow0 + tid];

        // ================= pipelined, K-split HMMA GEMM =================
        float d[4][4];
        #pragma unroll
        for (int nt = 0; nt < 4; ++nt)
            #pragma unroll
            for (int k = 0; k < 4; ++k) d[nt][k] = 0.0f;

        const int nchunk = start / CH;

        STAGE_CHUNK(0, 0u);            // prologue: chunk 0 -> buf0
        CP_COMMIT();

        for (int ci = 0; ci < nchunk; ++ci) {
            const uint bufoff = (uint)(ci & 1) * TILE_BYTES;
            if (ci + 1 < nchunk) {
                STAGE_CHUNK((ci + 1) * CH, (uint)((ci + 1) & 1) * TILE_BYTES);
                CP_COMMIT();
                CP_WAIT1();            // chunk ci's group complete
            } else {
                CP_WAIT0();
            }
            __syncthreads();           // buf[ci&1] visible to all warps

            const uint aA = smem_base + bufoff + oA;
            const uint aB = smem_base + bufoff + oB;
            #pragma unroll
            for (int kq = 0; kq < 4; ++kq) {
                const uint ko = (uint)(kh * 4 + kq) * 32;
                uint Ah[4], Al[4], Bh0[4], Bh1[4], Bl0[4], Bl1[4];
                ldsm_x4(Ah, aA + W_HI + ko);
                ldsm_x4(Al, aA + W_LO + ko);
                ldsm_x4(Bh0, aB + O_HI + ko);                      // n 0..15
                ldsm_x4(Bh1, aB + O_HI + 16 * WT_STRIDE + ko);     // n 16..31
                ldsm_x4(Bl0, aB + O_LO + ko);
                ldsm_x4(Bl1, aB + O_LO + 16 * WT_STRIDE + ko);
                // 3-pass split: Wh*oh + Wl*oh + Wh*ol
                mma16816(d[0], Ah, Bh0 + 0);  mma16816(d[1], Ah, Bh0 + 2);
                mma16816(d[2], Ah, Bh1 + 0);  mma16816(d[3], Ah, Bh1 + 2);
                mma16816(d[0], Al, Bh0 + 0);  mma16816(d[1], Al, Bh0 + 2);
                mma16816(d[2], Al, Bh1 + 0);  mma16816(d[3], Al, Bh1 + 2);
                mma16816(d[0], Ah, Bl0 + 0);  mma16816(d[1], Ah, Bl0 + 2);
                mma16816(d[2], Ah, Bl1 + 0);  mma16816(d[3], Ah, Bl1 + 2);
            }
            __syncthreads();           // all warps done reading buf[ci&1]
        }

        // ---- write K-half partial fragments into zsma / zsmb ----
        {
            float* zdst = kh ? zsmb : zsma;
            int rl = r0 + (lid >> 2), cb = (lid & 3) * 2;
            #pragma unroll
            for (int nt = 0; nt < 4; ++nt) {
                *(float2*)&zdst[rl * OS_PAD + nt * 8 + cb]       = make_float2(d[nt][0], d[nt][1]);
                *(float2*)&zdst[(rl + 8) * OS_PAD + nt * 8 + cb] = make_float2(d[nt][2], d[nt][3]);
            }
        }
        __syncthreads();

        // ---- stage in-block fp32 W tile (unions into dead tile buffers) ----
        float* wseq = (float*)smemc;
        for (int idx = tid; idx < KB * KB; idx += NTHR) {
            int n = idx / KB, j = idx % KB;
            wseq[n * WSEQ_PAD + j] = W[(size_t)(erow0 + n) * N_TOT + start + j];
        }
        __syncthreads();

        // ---- load z tile (sum of K-halves) into packed registers ----
        ull acc2[4][2];
        if (tid < 256) {
            #pragma unroll
            for (int k = 0; k < 4; ++k) {
                const float* za = zsma + (ng4 + k) * OS_PAD + cg * 4;
                const float* zb = zsmb + (ng4 + k) * OS_PAD + cg * 4;
                acc2[k][0] = pack2(za[0] + zb[0], za[1] + zb[1]);
                acc2[k][1] = pack2(za[2] + zb[2], za[3] + zb[3]);
            }
        }

        // ---- hierarchical sequential solve: 8 x (16-triangle + rank-16) ----
        for (int s = 0; s < 8; ++s) {
            if (tid < 256 && (ng >> 2) == s) {
                #pragma unroll
                for (int k = 0; k < 4; ++k)
                    #pragma unroll
                    for (int h = 0; h < 2; ++h) {
                        float2 v = unpack2(acc2[k][h]);
                        zsma[(ng4 + k) * OS_PAD + cg * 4 + 2 * h]     = v.x;
                        zsma[(ng4 + k) * OS_PAD + cg * 4 + 2 * h + 1] = v.y;
                    }
            }
            __syncthreads();

            if (tid < BT) {
                const int col  = tid;
                const int base = s * SUB;
                float oreg[SUB];
                #pragma unroll
                for (int i = 0; i < SUB; ++i) {
                    float z = zsma[(base + i) * OS_PAD + col] + bsm[base + i];
                    #pragma unroll
                    for (int j = 0; j < i; ++j)
                        z += wseq[(base + i) * WSEQ_PAD + (base + j)] * oreg[j];
                    float o = fast_sigmoid5(z);
                    oreg[i] = o;
                    osm_blk[(base + i) * OS_PAD + col] = o;
                }
            }
            __syncthreads();

            if (tid < 256 && ng >= 4 * (s + 1)) {
                #pragma unroll
                for (int j = 0; j < SUB; ++j) {
                    int jj = s * SUB + j;
                    const ull* o2 = (const ull*)&osm_blk[jj * OS_PAD + cg * 4];
                    ull o0 = o2[0], o1 = o2[1];
                    #pragma unroll
                    for (int k = 0; k < 4; ++k) {
                        float w = wseq[(ng4 + k) * WSEQ_PAD + jj];
                        ull wp = pack2(w, w);
                        ffma2(acc2[k][0], wp, o0);
                        ffma2(acc2[k][1], wp, o1);
                    }
                }
            }
        }
        __syncthreads();

        // ---- commit block outputs as bf16 hi/lo ([batch][node] layout) ----
        for (int idx = tid; idx < BT * (KB / 2); idx += NTHR) {
            int c = idx >> 6, j2 = idx & 63;
            float o0 = osm_blk[(2 * j2) * OS_PAD + c];
            float o1 = osm_blk[(2 * j2 + 1) * OS_PAD + c];
            ushort h0, h1, l0, l1;
            split_bf16(o0, h0, l0);
            split_bf16(o1, h1, l1);
            size_t g = (size_t)(c0 + c) * N_TOT + start + 2 * j2;
            *(uint*)(g_ohi + g) = ((uint)h1 << 16) | h0;
            *(uint*)(g_olo + g) = ((uint)l1 << 16) | l0;
        }
        if (start >= N_TOT - N_OUT) {
            const int off = start - (N_TOT - N_OUT);
            for (int idx = tid; idx < KB * BT; idx += NTHR) {
                int j = idx % KB, c = idx / KB;
                out[(c0 + c) * N_OUT + off + j] = osm_blk[j * OS_PAD + c];
            }
        }
        __syncthreads();   // commit visible before next block's prefetch
    }
}

extern "C" void kernel_launch(void* const* d_in, const int* in_sizes, int n_in,
                              void* d_out, int out_size)
{
    const float* x    = (const float*)d_in[0];
    const float* W    = (const float*)d_in[1];
    const float* bias = (const float*)d_in[2];
    float* out        = (float*)d_out;

    convW_kernel<<<(N_EV * N_TOT / 4) / 256, 256>>>(W);

    cudaFuncSetAttribute(neat_ff_kernel,
                         cudaFuncAttributeMaxDynamicSharedMemorySize, SMEM_BYTES);
    neat_ff_kernel<<<NCTA, NTHR, SMEM_BYTES>>>(x, W, bias, out);
}